// round 14
// baseline (speedup 1.0000x reference)
#include <cuda_runtime.h>
#include <cuda_bf16.h>
#include <math.h>
#include <stdint.h>

// Problem constants
#define BB 2
#define SS 2048
#define DM 1024
#define NH 16
#define DK 64
#define MROWS (BB * SS)                                  // 4096
#define OUT_ELEMS ((size_t)BB * SS * DM)                 // 4,194,304
#define ATT_ELEMS ((size_t)BB * NH * SS * SS)            // 134,217,728
#define HEADS (BB * NH)
#define HSZ ((size_t)SS * DK)                            // elems per head

// ---------------- helpers (all baseline PTX, legal on compute_103) ----------
__device__ __forceinline__ uint32_t smem_u32(const void* p) {
    uint32_t a;
    asm("{ .reg .u64 t; cvta.to.shared.u64 t, %1; cvt.u32.u64 %0, t; }" : "=r"(a) : "l"(p));
    return a;
}
__device__ __forceinline__ uint32_t sw128(uint32_t off) { return off ^ ((off >> 3) & 0x70); }

// pack two floats -> bf16x2 (lo = a, hi = b)
__device__ __forceinline__ uint32_t pkbf(float a, float b) {
    uint32_t r; asm("cvt.rn.bf16x2.f32 %0, %1, %2;" : "=r"(r) : "f"(b), "f"(a)); return r;
}
// unpack halves of bf16x2 back to float (exact)
__device__ __forceinline__ float bflo(uint32_t p) { return __uint_as_float(p << 16); }
__device__ __forceinline__ float bfhi(uint32_t p) { return __uint_as_float(p & 0xffff0000u); }

#define LDSM4(d, addr)                                                         \
    asm volatile("ldmatrix.sync.aligned.m8n8.x4.shared.b16 {%0,%1,%2,%3}, [%4];" \
        : "=r"((d)[0]), "=r"((d)[1]), "=r"((d)[2]), "=r"((d)[3]) : "r"(addr))
#define LDSM4T(d, addr)                                                        \
    asm volatile("ldmatrix.sync.aligned.m8n8.x4.trans.shared.b16 {%0,%1,%2,%3}, [%4];" \
        : "=r"((d)[0]), "=r"((d)[1]), "=r"((d)[2]), "=r"((d)[3]) : "r"(addr))

#define MMA_BF16(c, a, b0, b1)                                                 \
    asm volatile("mma.sync.aligned.m16n8k16.row.col.f32.bf16.bf16.f32 "        \
        "{%0,%1,%2,%3},{%4,%5,%6,%7},{%8,%9},{%0,%1,%2,%3};"                   \
        : "+f"((c)[0]), "+f"((c)[1]), "+f"((c)[2]), "+f"((c)[3])               \
        : "r"((a)[0]), "r"((a)[1]), "r"((a)[2]), "r"((a)[3]), "r"(b0), "r"(b1))

#define CP_ASYNC16(smem_addr, gptr)                                            \
    asm volatile("cp.async.cg.shared.global [%0], [%1], 16;"                   \
        :: "r"(smem_addr), "l"(gptr) : "memory")
#define CP_COMMIT  asm volatile("cp.async.commit_group;" ::: "memory")
#define CP_WAIT(n) asm volatile("cp.async.wait_group %0;" :: "n"(n) : "memory")

// ---------------- scratch (device globals; no allocation allowed) -----------
__device__ float g_Mv[HEADS * DK];          // sum_k mask[b,k] * Vh[b,h,k,d]

__device__ __align__(16) __nv_bfloat16 g_WThi[4 * DM * DM];       // W^T hi [n][k]
__device__ __align__(16) __nv_bfloat16 g_WTlo[4 * DM * DM];
__device__ __align__(16) __nv_bfloat16 g_Xhi[3 * MROWS * DM];     // q,k,v split
__device__ __align__(16) __nv_bfloat16 g_Xlo[3 * MROWS * DM];
__device__ __align__(16) __nv_bfloat16 g_QKVh[3 * HEADS * SS * DK]; // head-split hi
__device__ __align__(16) __nv_bfloat16 g_QKVl[3 * HEADS * SS * DK]; // head-split lo
__device__ __align__(16) __nv_bfloat16 g_Chi[MROWS * DM];          // ctx hi
__device__ __align__(16) __nv_bfloat16 g_Clo[MROWS * DM];

// =====================================================================
// prep: z<4 -> transpose+split W_z ; z>=4 -> split q/k/v activations
// =====================================================================
__global__ void prep_kernel(const float* __restrict__ q, const float* __restrict__ k,
                            const float* __restrict__ v,
                            const float* __restrict__ Wq, const float* __restrict__ Wk,
                            const float* __restrict__ Wv, const float* __restrict__ Wo)
{
    const int z = blockIdx.z;
    if (z < 4) {
        const float* W = (z == 0) ? Wq : (z == 1) ? Wk : (z == 2) ? Wv : Wo;
        __nv_bfloat16* hi = g_WThi + (size_t)z * DM * DM;
        __nv_bfloat16* lo = g_WTlo + (size_t)z * DM * DM;
        __shared__ float t[32][33];
        const int tx = threadIdx.x & 31, ty = threadIdx.x >> 5;
        const int N0 = blockIdx.x * 32, K0 = blockIdx.y * 32;
#pragma unroll
        for (int i = 0; i < 4; ++i)
            t[ty + 8 * i][tx] = W[(size_t)(K0 + ty + 8 * i) * DM + N0 + tx];
        __syncthreads();
#pragma unroll
        for (int i = 0; i < 4; ++i) {
            const float x = t[tx][ty + 8 * i];
            const __nv_bfloat16 h = __float2bfloat16(x);
            const __nv_bfloat16 l = __float2bfloat16(x - __bfloat162float(h));
            const size_t o = (size_t)(N0 + ty + 8 * i) * DM + K0 + tx;
            hi[o] = h; lo[o] = l;
        }
    } else {
        const float* src = (z == 4) ? q : (z == 5) ? k : v;
        __nv_bfloat16* hi = g_Xhi + (size_t)(z - 4) * MROWS * DM;
        __nv_bfloat16* lo = g_Xlo + (size_t)(z - 4) * MROWS * DM;
        const size_t t64 = (size_t)(blockIdx.y * 32 + blockIdx.x) * 256 + threadIdx.x;
#pragma unroll
        for (int j = 0; j < 4; ++j) {
            const size_t f4 = t64 * 4 + j;
            const float4 xv = *(const float4*)(src + f4 * 4);
            uint32_t ph0 = pkbf(xv.x, xv.y), ph1 = pkbf(xv.z, xv.w);
            uint32_t pl0 = pkbf(xv.x - bflo(ph0), xv.y - bfhi(ph0));
            uint32_t pl1 = pkbf(xv.z - bflo(ph1), xv.w - bfhi(ph1));
            uint2 uh = make_uint2(ph0, ph1), ulv = make_uint2(pl0, pl1);
            *(uint2*)(hi + f4 * 4) = uh;
            *(uint2*)(lo + f4 * 4) = ulv;
        }
    }
}

// =====================================================================
// bfgemm: C = A @ W^T + bias via mma.sync bf16, hi/lo split (3 products).
// headsplit==2: write bf16 hi/lo head-split to Oh/Ol (+z*oZ)
// headsplit==0: write fp32 row-major to C0.
// =====================================================================
#define STG 65536
#define GSMEM (2 * STG)

__global__ __launch_bounds__(256) void bfgemm(
    const __nv_bfloat16* __restrict__ Ahi, const __nv_bfloat16* __restrict__ Alo,
    size_t aZ,
    const __nv_bfloat16* __restrict__ Whi, const __nv_bfloat16* __restrict__ Wlo,
    size_t wZ,
    const float* __restrict__ b0, const float* __restrict__ b1,
    const float* __restrict__ b2,
    float* __restrict__ C0,
    __nv_bfloat16* __restrict__ Oh, __nv_bfloat16* __restrict__ Ol, size_t oZ,
    int headsplit)
{
    extern __shared__ __align__(16) char smem[];
    const uint32_t sb = smem_u32(smem);
    const int tid  = threadIdx.x;
    const int warp = tid >> 5;
    const int lane = tid & 31;
    const int wm   = warp & 1;
    const int wn   = warp >> 1;
    const int z    = blockIdx.z;

    const __nv_bfloat16* gAh = Ahi + (size_t)z * aZ + (size_t)blockIdx.y * 128 * DM;
    const __nv_bfloat16* gAl = Alo + (size_t)z * aZ + (size_t)blockIdx.y * 128 * DM;
    const __nv_bfloat16* gBh = Whi + (size_t)z * wZ + (size_t)blockIdx.x * 128 * DM;
    const __nv_bfloat16* gBl = Wlo + (size_t)z * wZ + (size_t)blockIdx.x * 128 * DM;
    const float* bias = (z == 0) ? b0 : (z == 1) ? b1 : b2;
    const int br = blockIdx.y * 128;
    const int bc = blockIdx.x * 128;

    float c[4][4][4];
#pragma unroll
    for (int i = 0; i < 4; ++i)
#pragma unroll
        for (int j = 0; j < 4; ++j)
#pragma unroll
            for (int r = 0; r < 4; ++r) c[i][j][r] = 0.f;

    const int ldRow = tid >> 3;
    const int ldKc  = tid & 7;
    const uint32_t soBase[4] = {
        sw128((uint32_t)((ldRow +  0) * 128 + ldKc * 16)),
        sw128((uint32_t)((ldRow + 32) * 128 + ldKc * 16)),
        sw128((uint32_t)((ldRow + 64) * 128 + ldKc * 16)),
        sw128((uint32_t)((ldRow + 96) * 128 + ldKc * 16)) };

#define ISSUE_STAGE(kt, stg) do {                                              \
    const int kof = (kt) * 64 + ldKc * 8;                                      \
    const uint32_t stb = sb + (stg) * STG;                                     \
    _Pragma("unroll")                                                          \
    for (int j = 0; j < 4; ++j) {                                              \
        const size_t go = (size_t)(ldRow + 32 * j) * DM + kof;                 \
        CP_ASYNC16(stb +         soBase[j], gAh + go);                         \
        CP_ASYNC16(stb + 16384 + soBase[j], gAl + go);                         \
        CP_ASYNC16(stb + 32768 + soBase[j], gBh + go);                         \
        CP_ASYNC16(stb + 49152 + soBase[j], gBl + go);                         \
    }                                                                          \
} while (0)

    ISSUE_STAGE(0, 0);
    CP_COMMIT;

    for (int kt = 0; kt < 16; ++kt) {
        if (kt < 15) { ISSUE_STAGE(kt + 1, (kt + 1) & 1); CP_COMMIT; CP_WAIT(1); }
        else         { CP_WAIT(0); }
        __syncthreads();

        const uint32_t stb = sb + (kt & 1) * STG;
#pragma unroll
        for (int s16 = 0; s16 < 4; ++s16) {
            const int kch = s16 * 2 + ((lane >> 4) & 1);
            uint32_t ahi[4][4], alo[4][4];
#pragma unroll
            for (int mt = 0; mt < 4; ++mt) {
                const int arow = wm * 64 + mt * 16 + (lane & 15);
                const uint32_t off = sw128((uint32_t)(arow * 128 + kch * 16));
                LDSM4(ahi[mt], stb + off);
                LDSM4(alo[mt], stb + 16384 + off);
            }
            uint32_t bhi[2][4], blo[2][4];
#pragma unroll
            for (int bt = 0; bt < 2; ++bt) {
                const int nrow = wn * 32 + bt * 16 + (lane & 15);
                const uint32_t off = sw128((uint32_t)(nrow * 128 + kch * 16));
                LDSM4(bhi[bt], stb + 32768 + off);
                LDSM4(blo[bt], stb + 49152 + off);
            }
#pragma unroll
            for (int mt = 0; mt < 4; ++mt)
#pragma unroll
                for (int bt = 0; bt < 2; ++bt)
#pragma unroll
                    for (int h = 0; h < 2; ++h) {
                        float* cc = c[mt][bt * 2 + h];
                        MMA_BF16(cc, ahi[mt], bhi[bt][h], bhi[bt][h + 2]);
                        MMA_BF16(cc, ahi[mt], blo[bt][h], blo[bt][h + 2]);
                        MMA_BF16(cc, alo[mt], bhi[bt][h], bhi[bt][h + 2]);
                    }
        }
        __syncthreads();
    }
#undef ISSUE_STAGE

    __nv_bfloat16* oh = Oh + (size_t)z * oZ;
    __nv_bfloat16* ol = Ol + (size_t)z * oZ;
    const int rl = lane >> 2, cl = (lane & 3) * 2;
#pragma unroll
    for (int mt = 0; mt < 4; ++mt) {
        const int m0 = br + wm * 64 + mt * 16 + rl;
#pragma unroll
        for (int j = 0; j < 4; ++j) {
            const int n0 = bc + wn * 32 + (j >> 1) * 16 + (j & 1) * 8 + cl;
            const float2 bi = *(const float2*)(bias + n0);
            float2 o0, o1;
            o0.x = c[mt][j][0] + bi.x;  o0.y = c[mt][j][1] + bi.y;
            o1.x = c[mt][j][2] + bi.x;  o1.y = c[mt][j][3] + bi.y;
            if (headsplit == 2) {
                const int h = n0 >> 6, d = n0 & (DK - 1);
                const int b0r = m0 >> 11, s0 = m0 & (SS - 1);
                const size_t p0 = (((size_t)(b0r * NH + h) * SS + s0) << 6) + d;
                uint32_t ph = pkbf(o0.x, o0.y);
                uint32_t pl = pkbf(o0.x - bflo(ph), o0.y - bfhi(ph));
                *(uint32_t*)&oh[p0] = ph;  *(uint32_t*)&ol[p0] = pl;
                const int m1 = m0 + 8;
                const int b1r = m1 >> 11, s1 = m1 & (SS - 1);
                const size_t p1 = (((size_t)(b1r * NH + h) * SS + s1) << 6) + d;
                ph = pkbf(o1.x, o1.y);
                pl = pkbf(o1.x - bflo(ph), o1.y - bfhi(ph));
                *(uint32_t*)&oh[p1] = ph;  *(uint32_t*)&ol[p1] = pl;
            } else {
                *(float2*)&C0[(size_t)m0 * DM + n0]       = o0;
                *(float2*)&C0[(size_t)(m0 + 8) * DM + n0] = o1;
            }
        }
    }
}

// =====================================================================
// maskv2: Mv[bh,d] = sum_k mask[b,k] * (Vhi+Vlo)[bh,k,d]
// =====================================================================
__global__ void maskv2(const float* __restrict__ mask,
                       const __nv_bfloat16* __restrict__ Vh,
                       const __nv_bfloat16* __restrict__ Vl,
                       float* __restrict__ Mv)
{
    __shared__ float red[8][64];
    const int d  = threadIdx.x & 63;
    const int kc = threadIdx.x >> 6;
    const int bh = blockIdx.x, b = bh >> 4;
    const __nv_bfloat16* vh = Vh + (size_t)bh * HSZ;
    const __nv_bfloat16* vl = Vl + (size_t)bh * HSZ;
    float acc = 0.f;
    for (int k = kc * 256; k < kc * 256 + 256; ++k) {
        const float m = mask[b * SS + k];
        acc += m * (__bfloat162float(vh[(size_t)k * 64 + d]) +
                    __bfloat162float(vl[(size_t)k * 64 + d]));
    }
    red[kc][d] = acc;
    __syncthreads();
    if (kc == 0) {
        float t = acc;
#pragma unroll
        for (int i = 1; i < 8; ++i) t += red[i][d];
        Mv[bh * 64 + d] = t;
    }
}

// =====================================================================
// attn_mma: fused attention on mma.sync bf16, full hi/lo split.
// Pass 1: QK + exp + lsum + PV (interleaved per n16).
// Pass 2: QK recompute (K from L2) with 3 INDEPENDENT accumulator
//         chains (ILP; registers free here) -> attw = e*invl - 1e9*mask,
//         written once via streaming stores.
// (Identical to the known-good R11 kernel except the pass-2 chains.)
// =====================================================================
#define AT_SQH 0
#define AT_SQL 16384        /* Q-lo; reused as 1e9*mask row after frag load */
#define AT_STG0 32768
#define AT_KSTG 65536       /* per stage: Khi,Klo,Vhi,Vlo @16KB */
#define AT_LSUM (AT_STG0 + 2 * AT_KSTG)
#define ATSMEM (AT_LSUM + 512)

__global__ __launch_bounds__(256, 1) void attn_mma(
    const __nv_bfloat16* __restrict__ Qbh, const __nv_bfloat16* __restrict__ Qbl,
    const __nv_bfloat16* __restrict__ Kbh, const __nv_bfloat16* __restrict__ Kbl,
    const __nv_bfloat16* __restrict__ Vbh, const __nv_bfloat16* __restrict__ Vbl,
    const float* __restrict__ Mv, const float* __restrict__ mask,
    float* __restrict__ attw,
    __nv_bfloat16* __restrict__ Chi, __nv_bfloat16* __restrict__ Clo)
{
    extern __shared__ __align__(16) char smem[];
    const uint32_t sb = smem_u32(smem);
    float* lsumS = (float*)(smem + AT_LSUM);
    float* maskS = (float*)(smem + AT_SQL);   // valid after kt==0 frag load

    const int tid  = threadIdx.x;
    const int warp = tid >> 5;
    const int lane = tid & 31;
    const int g    = lane >> 2;
    const int qd   = lane & 3;
    const int qt   = blockIdx.x;
    const int hh   = blockIdx.y;
    const int bz   = blockIdx.z;
    const int bh   = bz * NH + hh;

    const size_t hb = (size_t)bh * HSZ;
    const char* gQh = (const char*)(Qbh + hb + (size_t)qt * 128 * DK);
    const char* gQl = (const char*)(Qbl + hb + (size_t)qt * 128 * DK);
    const char* gKh = (const char*)(Kbh + hb);
    const char* gKl = (const char*)(Kbl + hb);
    const char* gVh = (const char*)(Vbh + hb);
    const char* gVl = (const char*)(Vbl + hb);
    const size_t attBase = ((size_t)bh * SS + (size_t)qt * 128) * SS;

    // ---- Q tiles via cp.async (with K/V stage 0) ----
#pragma unroll
    for (int i = 0; i < 4; ++i) {
        const int idx = tid + i * 256;
        const int row = idx >> 3, ch = idx & 7;
        const uint32_t so = sw128((uint32_t)(row * 128 + ch * 16));
        CP_ASYNC16(sb + AT_SQH + so, gQh + row * 128 + ch * 16);
        CP_ASYNC16(sb + AT_SQL + so, gQl + row * 128 + ch * 16);
    }

#define ISSUE_KV(kt, stg) do {                                                 \
    const uint32_t stb = sb + AT_STG0 + (stg) * AT_KSTG;                       \
    _Pragma("unroll")                                                          \
    for (int j = 0; j < 4; ++j) {                                              \
        const int idx = tid + j * 256;                                         \
        const int row = idx >> 3, ch = idx & 7;                                \
        const uint32_t so = sw128((uint32_t)(row * 128 + ch * 16));            \
        const int go = (kt) * 16384 + row * 128 + ch * 16;                     \
        CP_ASYNC16(stb +         so, gKh + go);                                \
        CP_ASYNC16(stb + 16384 + so, gKl + go);                                \
        CP_ASYNC16(stb + 32768 + so, gVh + go);                                \
        CP_ASYNC16(stb + 49152 + so, gVl + go);                                \
    }                                                                          \
} while (0)

#define ISSUE_K(kt, stg) do {                                                  \
    const uint32_t stb = sb + AT_STG0 + (stg) * AT_KSTG;                       \
    _Pragma("unroll")                                                          \
    for (int j = 0; j < 4; ++j) {                                              \
        const int idx = tid + j * 256;                                         \
        const int row = idx >> 3, ch = idx & 7;                                \
        const uint32_t so = sw128((uint32_t)(row * 128 + ch * 16));            \
        const int go = (kt) * 16384 + row * 128 + ch * 16;                     \
        CP_ASYNC16(stb +         so, gKh + go);                                \
        CP_ASYNC16(stb + 16384 + so, gKl + go);                                \
    }                                                                          \
} while (0)

    ISSUE_KV(0, 0);
    CP_COMMIT;

    uint32_t aQh[4][4], aQl[4][4];
    float pv[8][4];
#pragma unroll
    for (int i = 0; i < 8; ++i)
#pragma unroll
        for (int r = 0; r < 4; ++r) pv[i][r] = 0.f;
    float ls0 = 0.f, ls1 = 0.f;

    // =================== PASS 1: QK + exp + lsum + PV ===================
    for (int kt = 0; kt < 16; ++kt) {
        if (kt < 15) { ISSUE_KV(kt + 1, (kt + 1) & 1); CP_COMMIT; CP_WAIT(1); }
        else         { CP_WAIT(0); }
        __syncthreads();

        if (kt == 0) {
#pragma unroll
            for (int ks = 0; ks < 4; ++ks) {
                const uint32_t off = sw128((uint32_t)((warp * 16 + (lane & 15)) * 128
                                                      + ks * 32 + (lane >> 4) * 16));
                LDSM4(aQh[ks], sb + AT_SQH + off);
                LDSM4(aQl[ks], sb + AT_SQL + off);
            }
            __syncthreads();   // all frags read before maskS overwrites Q-lo
            const float* mrow = mask + bz * SS;
            for (int i = tid; i < 512; i += 256) {
                float4 mm = ((const float4*)mrow)[i];
                mm.x *= 1e9f; mm.y *= 1e9f; mm.z *= 1e9f; mm.w *= 1e9f;
                ((float4*)maskS)[i] = mm;
            }
        }

        const uint32_t stb = sb + AT_STG0 + (kt & 1) * AT_KSTG;

#pragma unroll
        for (int n16 = 0; n16 < 8; ++n16) {
            float s0[4] = {0.f, 0.f, 0.f, 0.f};
            float s1[4] = {0.f, 0.f, 0.f, 0.f};
#pragma unroll
            for (int ks = 0; ks < 4; ++ks) {
                uint32_t kh[4], kl[4];
                const uint32_t off = sw128((uint32_t)((n16 * 16 + (lane & 15)) * 128
                                                      + ks * 32 + (lane >> 4) * 16));
                LDSM4(kh, stb + off);
                LDSM4(kl, stb + 16384 + off);
                MMA_BF16(s0, aQh[ks], kh[0], kh[2]);
                MMA_BF16(s0, aQh[ks], kl[0], kl[2]);
                MMA_BF16(s0, aQl[ks], kh[0], kh[2]);
                MMA_BF16(s1, aQh[ks], kh[1], kh[3]);
                MMA_BF16(s1, aQh[ks], kl[1], kl[3]);
                MMA_BF16(s1, aQl[ks], kh[1], kh[3]);
            }
#pragma unroll
            for (int r = 0; r < 4; ++r) { s0[r] = __expf(s0[r] * 0.125f);
                                          s1[r] = __expf(s1[r] * 0.125f); }
            ls0 += s0[0] + s0[1] + s1[0] + s1[1];
            ls1 += s0[2] + s0[3] + s1[2] + s1[3];

            // hi/lo split -> transient P frags for this k16 chunk
            uint32_t aPh[4], aPl[4];
            uint32_t h0 = pkbf(s0[0], s0[1]);
            aPh[0] = h0; aPl[0] = pkbf(s0[0] - bflo(h0), s0[1] - bfhi(h0));
            uint32_t h1 = pkbf(s0[2], s0[3]);
            aPh[1] = h1; aPl[1] = pkbf(s0[2] - bflo(h1), s0[3] - bfhi(h1));
            uint32_t h2 = pkbf(s1[0], s1[1]);
            aPh[2] = h2; aPl[2] = pkbf(s1[0] - bflo(h2), s1[1] - bfhi(h2));
            uint32_t h3 = pkbf(s1[2], s1[3]);
            aPh[3] = h3; aPl[3] = pkbf(s1[2] - bflo(h3), s1[3] - bfhi(h3));

            // PV for this chunk: V rows n16*16..+15
#pragma unroll
            for (int d16 = 0; d16 < 4; ++d16) {
                uint32_t vh[4], vl[4];
                const uint32_t off = sw128((uint32_t)((n16 * 16 + (lane & 15)) * 128
                                                      + d16 * 32 + (lane >> 4) * 16));
                LDSM4T(vh, stb + 32768 + off);
                LDSM4T(vl, stb + 49152 + off);
#pragma unroll
                for (int h = 0; h < 2; ++h) {
                    float* cc = pv[d16 * 2 + h];
                    MMA_BF16(cc, aPh, vh[h * 2], vh[h * 2 + 1]);
                    MMA_BF16(cc, aPh, vl[h * 2], vl[h * 2 + 1]);
                    MMA_BF16(cc, aPl, vh[h * 2], vh[h * 2 + 1]);
                }
            }
        }
        __syncthreads();
    }
#undef ISSUE_KV

    // ---- row sums -> inverses ----
    float r0 = ls0;
    r0 += __shfl_xor_sync(0xffffffffu, r0, 1);
    r0 += __shfl_xor_sync(0xffffffffu, r0, 2);
    float r1 = ls1;
    r1 += __shfl_xor_sync(0xffffffffu, r1, 1);
    r1 += __shfl_xor_sync(0xffffffffu, r1, 2);
    if (qd == 0) { lsumS[warp * 16 + g] = r0; lsumS[warp * 16 + 8 + g] = r1; }
    __syncthreads();
    if (tid < 128) lsumS[tid] = 1.f / lsumS[tid];
    __syncthreads();

    const float i0 = lsumS[warp * 16 + g];
    const float i1 = lsumS[warp * 16 + 8 + g];

    // start pass-2 K prefetch before ctx epilogue (overlap)
    if (attw) { ISSUE_K(0, 0); CP_COMMIT; }

    // ---- ctx epilogue: bf16 hi/lo direct to Chi/Clo ----
    {
        const size_t row0 = ((size_t)bz * SS + qt * 128 + warp * 16 + g) * DM + hh * DK;
#pragma unroll
        for (int f = 0; f < 8; ++f) {
            const int d0 = f * 8 + qd * 2;
            const float2 mv = *(const float2*)&Mv[bh * DK + d0];
            const float o00 = pv[f][0] * i0 - 1e9f * mv.x;
            const float o01 = pv[f][1] * i0 - 1e9f * mv.y;
            const float o10 = pv[f][2] * i1 - 1e9f * mv.x;
            const float o11 = pv[f][3] * i1 - 1e9f * mv.y;
            uint32_t ph = pkbf(o00, o01);
            uint32_t pl = pkbf(o00 - bflo(ph), o01 - bfhi(ph));
            *(uint32_t*)&Chi[row0 + d0] = ph;
            *(uint32_t*)&Clo[row0 + d0] = pl;
            ph = pkbf(o10, o11);
            pl = pkbf(o10 - bflo(ph), o11 - bfhi(ph));
            *(uint32_t*)&Chi[row0 + 8 * DM + d0] = ph;
            *(uint32_t*)&Clo[row0 + 8 * DM + d0] = pl;
        }
    }

    // ========= PASS 2: recompute QK (3 indep chains), write attw ========
    if (attw) {
        for (int kt = 0; kt < 16; ++kt) {
            if (kt < 15) { ISSUE_K(kt + 1, (kt + 1) & 1); CP_COMMIT; CP_WAIT(1); }
            else         { CP_WAIT(0); }
            __syncthreads();

            const uint32_t stb = sb + AT_STG0 + (kt & 1) * AT_KSTG;
            float* prow = attw + attBase + (size_t)(warp * 16 + g) * SS + kt * 128;

#pragma unroll
            for (int n16 = 0; n16 < 8; ++n16) {
                // 3 independent accumulator chains per output half (ILP;
                // registers are free here: pv/ls retired after pass 1)
                float sA0[4] = {0,0,0,0}, sB0[4] = {0,0,0,0}, sC0[4] = {0,0,0,0};
                float sA1[4] = {0,0,0,0}, sB1[4] = {0,0,0,0}, sC1[4] = {0,0,0,0};
#pragma unroll
                for (int ks = 0; ks < 4; ++ks) {
                    uint32_t kh[4], kl[4];
                    const uint32_t off = sw128((uint32_t)((n16 * 16 + (lane & 15)) * 128
                                                          + ks * 32 + (lane >> 4) * 16));
                    LDSM4(kh, stb + off);
                    LDSM4(kl, stb + 16384 + off);
                    MMA_BF16(sA0, aQh[ks], kh[0], kh[2]);
                    MMA_BF16(sB0, aQh[ks], kl[0], kl[2]);
                    MMA_BF16(sC0, aQl[ks], kh[0], kh[2]);
                    MMA_BF16(sA1, aQh[ks], kh[1], kh[3]);
                    MMA_BF16(sB1, aQh[ks], kl[1], kl[3]);
                    MMA_BF16(sC1, aQl[ks], kh[1], kh[3]);
                }
                float s0[4], s1[4];
#pragma unroll
                for (int r = 0; r < 4; ++r) {
                    s0[r] = __expf((sA0[r] + sB0[r] + sC0[r]) * 0.125f);
                    s1[r] = __expf((sA1[r] + sB1[r] + sC1[r]) * 0.125f);
                }
                const float2 mA = *(const float2*)&maskS[kt * 128 + n16 * 16 + qd * 2];
                const float2 mB = *(const float2*)&maskS[kt * 128 + n16 * 16 + 8 + qd * 2];
                float* p = prow + n16 * 16 + qd * 2;
                __stcs((float2*)p,
                       make_float2(s0[0] * i0 - mA.x, s0[1] * i0 - mA.y));
                __stcs((float2*)(p + 8),
                       make_float2(s1[0] * i0 - mB.x, s1[1] * i0 - mB.y));
                __stcs((float2*)(p + 8 * SS),
                       make_float2(s0[2] * i1 - mA.x, s0[3] * i1 - mA.y));
                __stcs((float2*)(p + 8 * SS + 8),
                       make_float2(s1[2] * i1 - mB.x, s1[3] * i1 - mB.y));
            }
            __syncthreads();
        }
    }
#undef ISSUE_K
}

// =====================================================================
// launcher (4th launch = attn_mma -> profiled slot)
// =====================================================================
extern "C" void kernel_launch(void* const* d_in, const int* in_sizes, int n_in,
                              void* d_out, int out_size)
{
    const float* q    = (const float*)d_in[0];
    const float* k    = (const float*)d_in[1];
    const float* v    = (const float*)d_in[2];
    const float* mask = (const float*)d_in[3];
    const float* Wq   = (const float*)d_in[4];
    const float* bq   = (const float*)d_in[5];
    const float* Wk   = (const float*)d_in[6];
    const float* bk   = (const float*)d_in[7];
    const float* Wv   = (const float*)d_in[8];
    const float* bv   = (const float*)d_in[9];
    const float* Wo   = (const float*)d_in[10];
    const float* bo   = (const float*)d_in[11];

    float* out = (float*)d_out;
    const bool hasAtt = (size_t)out_size >= (OUT_ELEMS + ATT_ELEMS);
    float* attw = hasAtt ? (out + OUT_ELEMS) : nullptr;

    float *Mv;
    __nv_bfloat16 *WThi, *WTlo, *Xhi, *Xlo, *QKVh, *QKVl, *Chi, *Clo;
    cudaGetSymbolAddress((void**)&Mv,   g_Mv);
    cudaGetSymbolAddress((void**)&WThi, g_WThi);
    cudaGetSymbolAddress((void**)&WTlo, g_WTlo);
    cudaGetSymbolAddress((void**)&Xhi,  g_Xhi);
    cudaGetSymbolAddress((void**)&Xlo,  g_Xlo);
    cudaGetSymbolAddress((void**)&QKVh, g_QKVh);
    cudaGetSymbolAddress((void**)&QKVl, g_QKVl);
    cudaGetSymbolAddress((void**)&Chi,  g_Chi);
    cudaGetSymbolAddress((void**)&Clo,  g_Clo);

    cudaFuncSetAttribute(bfgemm, cudaFuncAttributeMaxDynamicSharedMemorySize, GSMEM);
    cudaFuncSetAttribute(attn_mma, cudaFuncAttributeMaxDynamicSharedMemorySize, ATSMEM);

    const size_t hZ = (size_t)HEADS * HSZ;

    // 1: convert W (transpose+split) + q/k/v activations (split)
    prep_kernel<<<dim3(32, 32, 7), 256>>>(q, k, v, Wq, Wk, Wv, Wo);

    // 2: Q/K/V projections -> bf16 hi/lo head-split
    bfgemm<<<dim3(DM / 128, MROWS / 128, 3), 256, GSMEM>>>(
        Xhi, Xlo, (size_t)MROWS * DM,
        WThi, WTlo, (size_t)DM * DM,
        bq, bk, bv, nullptr, QKVh, QKVl, hZ, 2);

    // 3: Mv from bf16 Vh
    maskv2<<<HEADS, 512>>>(mask, QKVh + 2 * hZ, QKVl + 2 * hZ, Mv);

    // 4: fused attention on tensor cores (profiled)
    attn_mma<<<dim3(SS / 128, NH, BB), 256, ATSMEM>>>(
        QKVh, QKVl, QKVh + hZ, QKVl + hZ, QKVh + 2 * hZ, QKVl + 2 * hZ,
        Mv, mask, attw, Chi, Clo);

    // 5: output projection (fp32 out)
    bfgemm<<<dim3(DM / 128, MROWS / 128, 1), 256, GSMEM>>>(
        Chi, Clo, 0,
        WThi + (size_t)3 * DM * DM, WTlo + (size_t)3 * DM * DM, 0,
        bo, bo, bo, out, Chi, Clo, 0, 0);
}

// round 15
// speedup vs baseline: 1.0096x; 1.0096x over previous
#include <cuda_runtime.h>
#include <cuda_bf16.h>
#include <math.h>
#include <stdint.h>

// Problem constants
#define BB 2
#define SS 2048
#define DM 1024
#define NH 16
#define DK 64
#define MROWS (BB * SS)                                  // 4096
#define OUT_ELEMS ((size_t)BB * SS * DM)                 // 4,194,304
#define ATT_ELEMS ((size_t)BB * NH * SS * SS)            // 134,217,728
#define HEADS (BB * NH)
#define HSZ ((size_t)SS * DK)                            // elems per head

// ---------------- helpers (all baseline PTX, legal on compute_103) ----------
__device__ __forceinline__ uint32_t smem_u32(const void* p) {
    uint32_t a;
    asm("{ .reg .u64 t; cvta.to.shared.u64 t, %1; cvt.u32.u64 %0, t; }" : "=r"(a) : "l"(p));
    return a;
}
__device__ __forceinline__ uint32_t sw128(uint32_t off) { return off ^ ((off >> 3) & 0x70); }

// pack two floats -> bf16x2 (lo = a, hi = b)
__device__ __forceinline__ uint32_t pkbf(float a, float b) {
    uint32_t r; asm("cvt.rn.bf16x2.f32 %0, %1, %2;" : "=r"(r) : "f"(b), "f"(a)); return r;
}
// unpack halves of bf16x2 back to float (exact)
__device__ __forceinline__ float bflo(uint32_t p) { return __uint_as_float(p << 16); }
__device__ __forceinline__ float bfhi(uint32_t p) { return __uint_as_float(p & 0xffff0000u); }

#define LDSM4(d, addr)                                                         \
    asm volatile("ldmatrix.sync.aligned.m8n8.x4.shared.b16 {%0,%1,%2,%3}, [%4];" \
        : "=r"((d)[0]), "=r"((d)[1]), "=r"((d)[2]), "=r"((d)[3]) : "r"(addr))
#define LDSM4T(d, addr)                                                        \
    asm volatile("ldmatrix.sync.aligned.m8n8.x4.trans.shared.b16 {%0,%1,%2,%3}, [%4];" \
        : "=r"((d)[0]), "=r"((d)[1]), "=r"((d)[2]), "=r"((d)[3]) : "r"(addr))

#define MMA_BF16(c, a, b0, b1)                                                 \
    asm volatile("mma.sync.aligned.m16n8k16.row.col.f32.bf16.bf16.f32 "        \
        "{%0,%1,%2,%3},{%4,%5,%6,%7},{%8,%9},{%0,%1,%2,%3};"                   \
        : "+f"((c)[0]), "+f"((c)[1]), "+f"((c)[2]), "+f"((c)[3])               \
        : "r"((a)[0]), "r"((a)[1]), "r"((a)[2]), "r"((a)[3]), "r"(b0), "r"(b1))

#define CP_ASYNC16(smem_addr, gptr)                                            \
    asm volatile("cp.async.cg.shared.global [%0], [%1], 16;"                   \
        :: "r"(smem_addr), "l"(gptr) : "memory")
#define CP_COMMIT  asm volatile("cp.async.commit_group;" ::: "memory")
#define CP_WAIT(n) asm volatile("cp.async.wait_group %0;" :: "n"(n) : "memory")

// ---------------- scratch (device globals; no allocation allowed) -----------
__device__ float g_Mv[HEADS * DK];          // sum_k mask[b,k] * Vh[b,h,k,d]

__device__ __align__(16) __nv_bfloat16 g_WThi[4 * DM * DM];       // W^T hi [n][k]
__device__ __align__(16) __nv_bfloat16 g_WTlo[4 * DM * DM];
__device__ __align__(16) __nv_bfloat16 g_Xhi[3 * MROWS * DM];     // q,k,v split
__device__ __align__(16) __nv_bfloat16 g_Xlo[3 * MROWS * DM];
__device__ __align__(16) __nv_bfloat16 g_QKVh[3 * HEADS * SS * DK]; // head-split hi
__device__ __align__(16) __nv_bfloat16 g_QKVl[3 * HEADS * SS * DK]; // head-split lo
__device__ __align__(16) __nv_bfloat16 g_Chi[MROWS * DM];          // ctx hi
__device__ __align__(16) __nv_bfloat16 g_Clo[MROWS * DM];

// =====================================================================
// prep: z<4 -> transpose+split W_z ; z>=4 -> split q/k/v activations
// =====================================================================
__global__ void prep_kernel(const float* __restrict__ q, const float* __restrict__ k,
                            const float* __restrict__ v,
                            const float* __restrict__ Wq, const float* __restrict__ Wk,
                            const float* __restrict__ Wv, const float* __restrict__ Wo)
{
    const int z = blockIdx.z;
    if (z < 4) {
        const float* W = (z == 0) ? Wq : (z == 1) ? Wk : (z == 2) ? Wv : Wo;
        __nv_bfloat16* hi = g_WThi + (size_t)z * DM * DM;
        __nv_bfloat16* lo = g_WTlo + (size_t)z * DM * DM;
        __shared__ float t[32][33];
        const int tx = threadIdx.x & 31, ty = threadIdx.x >> 5;
        const int N0 = blockIdx.x * 32, K0 = blockIdx.y * 32;
#pragma unroll
        for (int i = 0; i < 4; ++i)
            t[ty + 8 * i][tx] = W[(size_t)(K0 + ty + 8 * i) * DM + N0 + tx];
        __syncthreads();
#pragma unroll
        for (int i = 0; i < 4; ++i) {
            const float x = t[tx][ty + 8 * i];
            const __nv_bfloat16 h = __float2bfloat16(x);
            const __nv_bfloat16 l = __float2bfloat16(x - __bfloat162float(h));
            const size_t o = (size_t)(N0 + ty + 8 * i) * DM + K0 + tx;
            hi[o] = h; lo[o] = l;
        }
    } else {
        const float* src = (z == 4) ? q : (z == 5) ? k : v;
        __nv_bfloat16* hi = g_Xhi + (size_t)(z - 4) * MROWS * DM;
        __nv_bfloat16* lo = g_Xlo + (size_t)(z - 4) * MROWS * DM;
        const size_t t64 = (size_t)(blockIdx.y * 32 + blockIdx.x) * 256 + threadIdx.x;
#pragma unroll
        for (int j = 0; j < 4; ++j) {
            const size_t f4 = t64 * 4 + j;
            const float4 xv = *(const float4*)(src + f4 * 4);
            uint32_t ph0 = pkbf(xv.x, xv.y), ph1 = pkbf(xv.z, xv.w);
            uint32_t pl0 = pkbf(xv.x - bflo(ph0), xv.y - bfhi(ph0));
            uint32_t pl1 = pkbf(xv.z - bflo(ph1), xv.w - bfhi(ph1));
            uint2 uh = make_uint2(ph0, ph1), ulv = make_uint2(pl0, pl1);
            *(uint2*)(hi + f4 * 4) = uh;
            *(uint2*)(lo + f4 * 4) = ulv;
        }
    }
}

// =====================================================================
// bfgemm: C = A @ W^T + bias via mma.sync bf16, hi/lo split (3 products).
// headsplit==2: write bf16 hi/lo head-split to Oh/Ol (+z*oZ)
// headsplit==0: write fp32 row-major to C0.
// =====================================================================
#define STG 65536
#define GSMEM (2 * STG)

__global__ __launch_bounds__(256) void bfgemm(
    const __nv_bfloat16* __restrict__ Ahi, const __nv_bfloat16* __restrict__ Alo,
    size_t aZ,
    const __nv_bfloat16* __restrict__ Whi, const __nv_bfloat16* __restrict__ Wlo,
    size_t wZ,
    const float* __restrict__ b0, const float* __restrict__ b1,
    const float* __restrict__ b2,
    float* __restrict__ C0,
    __nv_bfloat16* __restrict__ Oh, __nv_bfloat16* __restrict__ Ol, size_t oZ,
    int headsplit)
{
    extern __shared__ __align__(16) char smem[];
    const uint32_t sb = smem_u32(smem);
    const int tid  = threadIdx.x;
    const int warp = tid >> 5;
    const int lane = tid & 31;
    const int wm   = warp & 1;
    const int wn   = warp >> 1;
    const int z    = blockIdx.z;

    const __nv_bfloat16* gAh = Ahi + (size_t)z * aZ + (size_t)blockIdx.y * 128 * DM;
    const __nv_bfloat16* gAl = Alo + (size_t)z * aZ + (size_t)blockIdx.y * 128 * DM;
    const __nv_bfloat16* gBh = Whi + (size_t)z * wZ + (size_t)blockIdx.x * 128 * DM;
    const __nv_bfloat16* gBl = Wlo + (size_t)z * wZ + (size_t)blockIdx.x * 128 * DM;
    const float* bias = (z == 0) ? b0 : (z == 1) ? b1 : b2;
    const int br = blockIdx.y * 128;
    const int bc = blockIdx.x * 128;

    float c[4][4][4];
#pragma unroll
    for (int i = 0; i < 4; ++i)
#pragma unroll
        for (int j = 0; j < 4; ++j)
#pragma unroll
            for (int r = 0; r < 4; ++r) c[i][j][r] = 0.f;

    const int ldRow = tid >> 3;
    const int ldKc  = tid & 7;
    const uint32_t soBase[4] = {
        sw128((uint32_t)((ldRow +  0) * 128 + ldKc * 16)),
        sw128((uint32_t)((ldRow + 32) * 128 + ldKc * 16)),
        sw128((uint32_t)((ldRow + 64) * 128 + ldKc * 16)),
        sw128((uint32_t)((ldRow + 96) * 128 + ldKc * 16)) };

#define ISSUE_STAGE(kt, stg) do {                                              \
    const int kof = (kt) * 64 + ldKc * 8;                                      \
    const uint32_t stb = sb + (stg) * STG;                                     \
    _Pragma("unroll")                                                          \
    for (int j = 0; j < 4; ++j) {                                              \
        const size_t go = (size_t)(ldRow + 32 * j) * DM + kof;                 \
        CP_ASYNC16(stb +         soBase[j], gAh + go);                         \
        CP_ASYNC16(stb + 16384 + soBase[j], gAl + go);                         \
        CP_ASYNC16(stb + 32768 + soBase[j], gBh + go);                         \
        CP_ASYNC16(stb + 49152 + soBase[j], gBl + go);                         \
    }                                                                          \
} while (0)

    ISSUE_STAGE(0, 0);
    CP_COMMIT;

    for (int kt = 0; kt < 16; ++kt) {
        if (kt < 15) { ISSUE_STAGE(kt + 1, (kt + 1) & 1); CP_COMMIT; CP_WAIT(1); }
        else         { CP_WAIT(0); }
        __syncthreads();

        const uint32_t stb = sb + (kt & 1) * STG;
#pragma unroll
        for (int s16 = 0; s16 < 4; ++s16) {
            const int kch = s16 * 2 + ((lane >> 4) & 1);
            uint32_t ahi[4][4], alo[4][4];
#pragma unroll
            for (int mt = 0; mt < 4; ++mt) {
                const int arow = wm * 64 + mt * 16 + (lane & 15);
                const uint32_t off = sw128((uint32_t)(arow * 128 + kch * 16));
                LDSM4(ahi[mt], stb + off);
                LDSM4(alo[mt], stb + 16384 + off);
            }
            uint32_t bhi[2][4], blo[2][4];
#pragma unroll
            for (int bt = 0; bt < 2; ++bt) {
                const int nrow = wn * 32 + bt * 16 + (lane & 15);
                const uint32_t off = sw128((uint32_t)(nrow * 128 + kch * 16));
                LDSM4(bhi[bt], stb + 32768 + off);
                LDSM4(blo[bt], stb + 49152 + off);
            }
#pragma unroll
            for (int mt = 0; mt < 4; ++mt)
#pragma unroll
                for (int bt = 0; bt < 2; ++bt)
#pragma unroll
                    for (int h = 0; h < 2; ++h) {
                        float* cc = c[mt][bt * 2 + h];
                        MMA_BF16(cc, ahi[mt], bhi[bt][h], bhi[bt][h + 2]);
                        MMA_BF16(cc, ahi[mt], blo[bt][h], blo[bt][h + 2]);
                        MMA_BF16(cc, alo[mt], bhi[bt][h], bhi[bt][h + 2]);
                    }
        }
        __syncthreads();
    }
#undef ISSUE_STAGE

    __nv_bfloat16* oh = Oh + (size_t)z * oZ;
    __nv_bfloat16* ol = Ol + (size_t)z * oZ;
    const int rl = lane >> 2, cl = (lane & 3) * 2;
#pragma unroll
    for (int mt = 0; mt < 4; ++mt) {
        const int m0 = br + wm * 64 + mt * 16 + rl;
#pragma unroll
        for (int j = 0; j < 4; ++j) {
            const int n0 = bc + wn * 32 + (j >> 1) * 16 + (j & 1) * 8 + cl;
            const float2 bi = *(const float2*)(bias + n0);
            float2 o0, o1;
            o0.x = c[mt][j][0] + bi.x;  o0.y = c[mt][j][1] + bi.y;
            o1.x = c[mt][j][2] + bi.x;  o1.y = c[mt][j][3] + bi.y;
            if (headsplit == 2) {
                const int h = n0 >> 6, d = n0 & (DK - 1);
                const int b0r = m0 >> 11, s0 = m0 & (SS - 1);
                const size_t p0 = (((size_t)(b0r * NH + h) * SS + s0) << 6) + d;
                uint32_t ph = pkbf(o0.x, o0.y);
                uint32_t pl = pkbf(o0.x - bflo(ph), o0.y - bfhi(ph));
                *(uint32_t*)&oh[p0] = ph;  *(uint32_t*)&ol[p0] = pl;
                const int m1 = m0 + 8;
                const int b1r = m1 >> 11, s1 = m1 & (SS - 1);
                const size_t p1 = (((size_t)(b1r * NH + h) * SS + s1) << 6) + d;
                ph = pkbf(o1.x, o1.y);
                pl = pkbf(o1.x - bflo(ph), o1.y - bfhi(ph));
                *(uint32_t*)&oh[p1] = ph;  *(uint32_t*)&ol[p1] = pl;
            } else {
                *(float2*)&C0[(size_t)m0 * DM + n0]       = o0;
                *(float2*)&C0[(size_t)(m0 + 8) * DM + n0] = o1;
            }
        }
    }
}

// =====================================================================
// maskv2: Mv[bh,d] = sum_k mask[b,k] * (Vhi+Vlo)[bh,k,d]
// =====================================================================
__global__ void maskv2(const float* __restrict__ mask,
                       const __nv_bfloat16* __restrict__ Vh,
                       const __nv_bfloat16* __restrict__ Vl,
                       float* __restrict__ Mv)
{
    __shared__ float red[8][64];
    const int d  = threadIdx.x & 63;
    const int kc = threadIdx.x >> 6;
    const int bh = blockIdx.x, b = bh >> 4;
    const __nv_bfloat16* vh = Vh + (size_t)bh * HSZ;
    const __nv_bfloat16* vl = Vl + (size_t)bh * HSZ;
    float acc = 0.f;
    for (int k = kc * 256; k < kc * 256 + 256; ++k) {
        const float m = mask[b * SS + k];
        acc += m * (__bfloat162float(vh[(size_t)k * 64 + d]) +
                    __bfloat162float(vl[(size_t)k * 64 + d]));
    }
    red[kc][d] = acc;
    __syncthreads();
    if (kc == 0) {
        float t = acc;
#pragma unroll
        for (int i = 1; i < 8; ++i) t += red[i][d];
        Mv[bh * 64 + d] = t;
    }
}

// =====================================================================
// attn_mma: fused attention on mma.sync bf16, full hi/lo split.
// OCCUPANCY build: single-buffered K/V smem (Q 32K + KV 64K + lsum),
// reg cap 128 via __launch_bounds__(256, 2) -> 2 CTAs/SM (16 warps).
// Cross-CTA overlap replaces intra-CTA double buffering.
// Pass 1: QK + exp + lsum + PV (interleaved per n16).
// Pass 2: QK recompute (serial chains, R11 form) -> attw streamed once.
// =====================================================================
#define AT_SQH 0
#define AT_SQL 16384        /* Q-lo; reused as 1e9*mask row after frag load */
#define AT_STG0 32768       /* single stage: Khi,Klo,Vhi,Vlo @16KB */
#define AT_LSUM (AT_STG0 + 65536)       /* 98304 */
#define ATSMEM (AT_LSUM + 512)          /* 98816 -> 2 CTAs/SM */

__global__ void __launch_bounds__(256, 2) attn_mma(
    const __nv_bfloat16* __restrict__ Qbh, const __nv_bfloat16* __restrict__ Qbl,
    const __nv_bfloat16* __restrict__ Kbh, const __nv_bfloat16* __restrict__ Kbl,
    const __nv_bfloat16* __restrict__ Vbh, const __nv_bfloat16* __restrict__ Vbl,
    const float* __restrict__ Mv, const float* __restrict__ mask,
    float* __restrict__ attw,
    __nv_bfloat16* __restrict__ Chi, __nv_bfloat16* __restrict__ Clo)
{
    extern __shared__ __align__(16) char smem[];
    const uint32_t sb = smem_u32(smem);
    float* lsumS = (float*)(smem + AT_LSUM);
    float* maskS = (float*)(smem + AT_SQL);   // valid after kt==0 frag load

    const int tid  = threadIdx.x;
    const int warp = tid >> 5;
    const int lane = tid & 31;
    const int g    = lane >> 2;
    const int qd   = lane & 3;
    const int qt   = blockIdx.x;
    const int hh   = blockIdx.y;
    const int bz   = blockIdx.z;
    const int bh   = bz * NH + hh;

    const size_t hb = (size_t)bh * HSZ;
    const char* gQh = (const char*)(Qbh + hb + (size_t)qt * 128 * DK);
    const char* gQl = (const char*)(Qbl + hb + (size_t)qt * 128 * DK);
    const char* gKh = (const char*)(Kbh + hb);
    const char* gKl = (const char*)(Kbl + hb);
    const char* gVh = (const char*)(Vbh + hb);
    const char* gVl = (const char*)(Vbl + hb);
    const size_t attBase = ((size_t)bh * SS + (size_t)qt * 128) * SS;

    // ---- Q tiles via cp.async (with K/V tile 0) ----
#pragma unroll
    for (int i = 0; i < 4; ++i) {
        const int idx = tid + i * 256;
        const int row = idx >> 3, ch = idx & 7;
        const uint32_t so = sw128((uint32_t)(row * 128 + ch * 16));
        CP_ASYNC16(sb + AT_SQH + so, gQh + row * 128 + ch * 16);
        CP_ASYNC16(sb + AT_SQL + so, gQl + row * 128 + ch * 16);
    }

#define ISSUE_KV(kt) do {                                                      \
    const uint32_t stb = sb + AT_STG0;                                         \
    _Pragma("unroll")                                                          \
    for (int j = 0; j < 4; ++j) {                                              \
        const int idx = tid + j * 256;                                         \
        const int row = idx >> 3, ch = idx & 7;                                \
        const uint32_t so = sw128((uint32_t)(row * 128 + ch * 16));            \
        const int go = (kt) * 16384 + row * 128 + ch * 16;                     \
        CP_ASYNC16(stb +         so, gKh + go);                                \
        CP_ASYNC16(stb + 16384 + so, gKl + go);                                \
        CP_ASYNC16(stb + 32768 + so, gVh + go);                                \
        CP_ASYNC16(stb + 49152 + so, gVl + go);                                \
    }                                                                          \
} while (0)

#define ISSUE_K(kt) do {                                                       \
    const uint32_t stb = sb + AT_STG0;                                         \
    _Pragma("unroll")                                                          \
    for (int j = 0; j < 4; ++j) {                                              \
        const int idx = tid + j * 256;                                         \
        const int row = idx >> 3, ch = idx & 7;                                \
        const uint32_t so = sw128((uint32_t)(row * 128 + ch * 16));            \
        const int go = (kt) * 16384 + row * 128 + ch * 16;                     \
        CP_ASYNC16(stb +         so, gKh + go);                                \
        CP_ASYNC16(stb + 16384 + so, gKl + go);                                \
    }                                                                          \
} while (0)

    ISSUE_KV(0);
    CP_COMMIT;

    uint32_t aQh[4][4], aQl[4][4];
    float pv[8][4];
#pragma unroll
    for (int i = 0; i < 8; ++i)
#pragma unroll
        for (int r = 0; r < 4; ++r) pv[i][r] = 0.f;
    float ls0 = 0.f, ls1 = 0.f;

    // =================== PASS 1: QK + exp + lsum + PV ===================
    for (int kt = 0; kt < 16; ++kt) {
        CP_WAIT(0);
        __syncthreads();

        if (kt == 0) {
#pragma unroll
            for (int ks = 0; ks < 4; ++ks) {
                const uint32_t off = sw128((uint32_t)((warp * 16 + (lane & 15)) * 128
                                                      + ks * 32 + (lane >> 4) * 16));
                LDSM4(aQh[ks], sb + AT_SQH + off);
                LDSM4(aQl[ks], sb + AT_SQL + off);
            }
            __syncthreads();   // all frags read before maskS overwrites Q-lo
            const float* mrow = mask + bz * SS;
            for (int i = tid; i < 512; i += 256) {
                float4 mm = ((const float4*)mrow)[i];
                mm.x *= 1e9f; mm.y *= 1e9f; mm.z *= 1e9f; mm.w *= 1e9f;
                ((float4*)maskS)[i] = mm;
            }
        }

        const uint32_t stb = sb + AT_STG0;

#pragma unroll
        for (int n16 = 0; n16 < 8; ++n16) {
            float s0[4] = {0.f, 0.f, 0.f, 0.f};
            float s1[4] = {0.f, 0.f, 0.f, 0.f};
#pragma unroll
            for (int ks = 0; ks < 4; ++ks) {
                uint32_t kh[4], kl[4];
                const uint32_t off = sw128((uint32_t)((n16 * 16 + (lane & 15)) * 128
                                                      + ks * 32 + (lane >> 4) * 16));
                LDSM4(kh, stb + off);
                LDSM4(kl, stb + 16384 + off);
                MMA_BF16(s0, aQh[ks], kh[0], kh[2]);
                MMA_BF16(s0, aQh[ks], kl[0], kl[2]);
                MMA_BF16(s0, aQl[ks], kh[0], kh[2]);
                MMA_BF16(s1, aQh[ks], kh[1], kh[3]);
                MMA_BF16(s1, aQh[ks], kl[1], kl[3]);
                MMA_BF16(s1, aQl[ks], kh[1], kh[3]);
            }
#pragma unroll
            for (int r = 0; r < 4; ++r) { s0[r] = __expf(s0[r] * 0.125f);
                                          s1[r] = __expf(s1[r] * 0.125f); }
            ls0 += s0[0] + s0[1] + s1[0] + s1[1];
            ls1 += s0[2] + s0[3] + s1[2] + s1[3];

            // hi/lo split -> transient P frags for this k16 chunk
            uint32_t aPh[4], aPl[4];
            uint32_t h0 = pkbf(s0[0], s0[1]);
            aPh[0] = h0; aPl[0] = pkbf(s0[0] - bflo(h0), s0[1] - bfhi(h0));
            uint32_t h1 = pkbf(s0[2], s0[3]);
            aPh[1] = h1; aPl[1] = pkbf(s0[2] - bflo(h1), s0[3] - bfhi(h1));
            uint32_t h2 = pkbf(s1[0], s1[1]);
            aPh[2] = h2; aPl[2] = pkbf(s1[0] - bflo(h2), s1[1] - bfhi(h2));
            uint32_t h3 = pkbf(s1[2], s1[3]);
            aPh[3] = h3; aPl[3] = pkbf(s1[2] - bflo(h3), s1[3] - bfhi(h3));

            // PV for this chunk: V rows n16*16..+15
#pragma unroll
            for (int d16 = 0; d16 < 4; ++d16) {
                uint32_t vh[4], vl[4];
                const uint32_t off = sw128((uint32_t)((n16 * 16 + (lane & 15)) * 128
                                                      + d16 * 32 + (lane >> 4) * 16));
                LDSM4T(vh, stb + 32768 + off);
                LDSM4T(vl, stb + 49152 + off);
#pragma unroll
                for (int h = 0; h < 2; ++h) {
                    float* cc = pv[d16 * 2 + h];
                    MMA_BF16(cc, aPh, vh[h * 2], vh[h * 2 + 1]);
                    MMA_BF16(cc, aPh, vl[h * 2], vl[h * 2 + 1]);
                    MMA_BF16(cc, aPl, vh[h * 2], vh[h * 2 + 1]);
                }
            }
        }
        __syncthreads();   // everyone done reading tile before overwrite
        if (kt < 15) { ISSUE_KV(kt + 1); CP_COMMIT; }
    }
#undef ISSUE_KV

    // ---- row sums -> inverses ----
    float r0 = ls0;
    r0 += __shfl_xor_sync(0xffffffffu, r0, 1);
    r0 += __shfl_xor_sync(0xffffffffu, r0, 2);
    float r1 = ls1;
    r1 += __shfl_xor_sync(0xffffffffu, r1, 1);
    r1 += __shfl_xor_sync(0xffffffffu, r1, 2);
    if (qd == 0) { lsumS[warp * 16 + g] = r0; lsumS[warp * 16 + 8 + g] = r1; }
    __syncthreads();
    if (tid < 128) lsumS[tid] = 1.f / lsumS[tid];
    __syncthreads();

    const float i0 = lsumS[warp * 16 + g];
    const float i1 = lsumS[warp * 16 + 8 + g];

    // start pass-2 K prefetch before ctx epilogue (overlap)
    if (attw) { ISSUE_K(0); CP_COMMIT; }

    // ---- ctx epilogue: bf16 hi/lo direct to Chi/Clo ----
    {
        const size_t row0 = ((size_t)bz * SS + qt * 128 + warp * 16 + g) * DM + hh * DK;
#pragma unroll
        for (int f = 0; f < 8; ++f) {
            const int d0 = f * 8 + qd * 2;
            const float2 mv = *(const float2*)&Mv[bh * DK + d0];
            const float o00 = pv[f][0] * i0 - 1e9f * mv.x;
            const float o01 = pv[f][1] * i0 - 1e9f * mv.y;
            const float o10 = pv[f][2] * i1 - 1e9f * mv.x;
            const float o11 = pv[f][3] * i1 - 1e9f * mv.y;
            uint32_t ph = pkbf(o00, o01);
            uint32_t pl = pkbf(o00 - bflo(ph), o01 - bfhi(ph));
            *(uint32_t*)&Chi[row0 + d0] = ph;
            *(uint32_t*)&Clo[row0 + d0] = pl;
            ph = pkbf(o10, o11);
            pl = pkbf(o10 - bflo(ph), o11 - bfhi(ph));
            *(uint32_t*)&Chi[row0 + 8 * DM + d0] = ph;
            *(uint32_t*)&Clo[row0 + 8 * DM + d0] = pl;
        }
    }

    // ========= PASS 2: recompute QK (serial chains), write attw =========
    if (attw) {
        for (int kt = 0; kt < 16; ++kt) {
            CP_WAIT(0);
            __syncthreads();

            const uint32_t stb = sb + AT_STG0;
            float* prow = attw + attBase + (size_t)(warp * 16 + g) * SS + kt * 128;

#pragma unroll
            for (int n16 = 0; n16 < 8; ++n16) {
                float s0[4] = {0.f, 0.f, 0.f, 0.f};
                float s1[4] = {0.f, 0.f, 0.f, 0.f};
#pragma unroll
                for (int ks = 0; ks < 4; ++ks) {
                    uint32_t kh[4], kl[4];
                    const uint32_t off = sw128((uint32_t)((n16 * 16 + (lane & 15)) * 128
                                                          + ks * 32 + (lane >> 4) * 16));
                    LDSM4(kh, stb + off);
                    LDSM4(kl, stb + 16384 + off);
                    MMA_BF16(s0, aQh[ks], kh[0], kh[2]);
                    MMA_BF16(s0, aQh[ks], kl[0], kl[2]);
                    MMA_BF16(s0, aQl[ks], kh[0], kh[2]);
                    MMA_BF16(s1, aQh[ks], kh[1], kh[3]);
                    MMA_BF16(s1, aQh[ks], kl[1], kl[3]);
                    MMA_BF16(s1, aQl[ks], kh[1], kh[3]);
                }
#pragma unroll
                for (int r = 0; r < 4; ++r) { s0[r] = __expf(s0[r] * 0.125f);
                                              s1[r] = __expf(s1[r] * 0.125f); }
                const float2 mA = *(const float2*)&maskS[kt * 128 + n16 * 16 + qd * 2];
                const float2 mB = *(const float2*)&maskS[kt * 128 + n16 * 16 + 8 + qd * 2];
                float* p = prow + n16 * 16 + qd * 2;
                __stcs((float2*)p,
                       make_float2(s0[0] * i0 - mA.x, s0[1] * i0 - mA.y));
                __stcs((float2*)(p + 8),
                       make_float2(s1[0] * i0 - mB.x, s1[1] * i0 - mB.y));
                __stcs((float2*)(p + 8 * SS),
                       make_float2(s0[2] * i1 - mA.x, s0[3] * i1 - mA.y));
                __stcs((float2*)(p + 8 * SS + 8),
                       make_float2(s1[2] * i1 - mB.x, s1[3] * i1 - mB.y));
            }
            __syncthreads();
            if (kt < 15) { ISSUE_K(kt + 1); CP_COMMIT; }
        }
    }
#undef ISSUE_K
}

// =====================================================================
// launcher (4th launch = attn_mma -> profiled slot)
// =====================================================================
extern "C" void kernel_launch(void* const* d_in, const int* in_sizes, int n_in,
                              void* d_out, int out_size)
{
    const float* q    = (const float*)d_in[0];
    const float* k    = (const float*)d_in[1];
    const float* v    = (const float*)d_in[2];
    const float* mask = (const float*)d_in[3];
    const float* Wq   = (const float*)d_in[4];
    const float* bq   = (const float*)d_in[5];
    const float* Wk   = (const float*)d_in[6];
    const float* bk   = (const float*)d_in[7];
    const float* Wv   = (const float*)d_in[8];
    const float* bv   = (const float*)d_in[9];
    const float* Wo   = (const float*)d_in[10];
    const float* bo   = (const float*)d_in[11];

    float* out = (float*)d_out;
    const bool hasAtt = (size_t)out_size >= (OUT_ELEMS + ATT_ELEMS);
    float* attw = hasAtt ? (out + OUT_ELEMS) : nullptr;

    float *Mv;
    __nv_bfloat16 *WThi, *WTlo, *Xhi, *Xlo, *QKVh, *QKVl, *Chi, *Clo;
    cudaGetSymbolAddress((void**)&Mv,   g_Mv);
    cudaGetSymbolAddress((void**)&WThi, g_WThi);
    cudaGetSymbolAddress((void**)&WTlo, g_WTlo);
    cudaGetSymbolAddress((void**)&Xhi,  g_Xhi);
    cudaGetSymbolAddress((void**)&Xlo,  g_Xlo);
    cudaGetSymbolAddress((void**)&QKVh, g_QKVh);
    cudaGetSymbolAddress((void**)&QKVl, g_QKVl);
    cudaGetSymbolAddress((void**)&Chi,  g_Chi);
    cudaGetSymbolAddress((void**)&Clo,  g_Clo);

    cudaFuncSetAttribute(bfgemm, cudaFuncAttributeMaxDynamicSharedMemorySize, GSMEM);
    cudaFuncSetAttribute(attn_mma, cudaFuncAttributeMaxDynamicSharedMemorySize, ATSMEM);

    const size_t hZ = (size_t)HEADS * HSZ;

    // 1: convert W (transpose+split) + q/k/v activations (split)
    prep_kernel<<<dim3(32, 32, 7), 256>>>(q, k, v, Wq, Wk, Wv, Wo);

    // 2: Q/K/V projections -> bf16 hi/lo head-split
    bfgemm<<<dim3(DM / 128, MROWS / 128, 3), 256, GSMEM>>>(
        Xhi, Xlo, (size_t)MROWS * DM,
        WThi, WTlo, (size_t)DM * DM,
        bq, bk, bv, nullptr, QKVh, QKVl, hZ, 2);

    // 3: Mv from bf16 Vh
    maskv2<<<HEADS, 512>>>(mask, QKVh + 2 * hZ, QKVl + 2 * hZ, Mv);

    // 4: fused attention on tensor cores (profiled)
    attn_mma<<<dim3(SS / 128, NH, BB), 256, ATSMEM>>>(
        QKVh, QKVl, QKVh + hZ, QKVl + hZ, QKVh + 2 * hZ, QKVl + 2 * hZ,
        Mv, mask, attw, Chi, Clo);

    // 5: output projection (fp32 out)
    bfgemm<<<dim3(DM / 128, MROWS / 128, 1), 256, GSMEM>>>(
        Chi, Clo, 0,
        WThi + (size_t)3 * DM * DM, WTlo + (size_t)3 * DM * DM, 0,
        bo, bo, bo, out, Chi, Clo, 0, 0);
}